// round 15
// baseline (speedup 1.0000x reference)
#include <cuda_runtime.h>
#include <math.h>

#define N_NODES 50000
#define N_EDGES 400000

// ---------------- scratch (static device globals; no allocation) ----------------
__device__ float g_erA[(size_t)N_EDGES * 64];
__device__ float g_eaA[(size_t)N_EDGES * 64];
__device__ float g_msg[(size_t)N_NODES * 256];
__device__ float g_nodesA[(size_t)N_NODES * 128];
__device__ float g_nodesB[(size_t)N_NODES * 128];
__device__ float g_deg[N_NODES];
__device__ float g_inv[N_NODES];   // 1/sqrt(deg)
__device__ float g_rdeg[N_NODES];  // 1/deg
__device__ int   g_perm[2 * N_NODES];
__device__ int   g_cnt[2];

// ---------------- f32x2 helpers ----------------
__device__ __forceinline__ unsigned long long packdup(float x) {
    unsigned long long r; unsigned int u = __float_as_uint(x);
    asm("mov.b64 %0, {%1, %1};" : "=l"(r) : "r"(u));
    return r;
}
__device__ __forceinline__ void ffma2(unsigned long long& acc, unsigned long long a, unsigned long long w) {
    asm("fma.rn.f32x2 %0, %1, %2, %0;" : "+l"(acc) : "l"(a), "l"(w));
}
__device__ __forceinline__ void unpack2(unsigned long long v, float& lo, float& hi) {
    unsigned int a, b;
    asm("mov.b64 {%0, %1}, %2;" : "=r"(a), "=r"(b) : "l"(v));
    lo = __uint_as_float(a); hi = __uint_as_float(b);
}
__device__ __forceinline__ void lds_wpair(unsigned int addr, unsigned long long& w01, unsigned long long& w23) {
    asm volatile("ld.shared.v2.b64 {%0, %1}, [%2];" : "=l"(w01), "=l"(w23) : "r"(addr));
}

// ---------------- weight staging: gmem -> regs -> smem (ping-pong) ----------------
template<int DOUT, int DOUT_PAD>
__device__ __forceinline__ void loadW_regs(const float* __restrict__ W, int k0, float2* wr) {
    constexpr int NW = DOUT_PAD / 32;
    constexpr int HALF = DOUT_PAD / 2;
#pragma unroll
    for (int i = 0; i < NW; i++) {
        int idx = threadIdx.x + i * 256;
        int kk = idx / HALF, oc = idx % HALF;
        int col = 2 * oc;
        float2 v = make_float2(0.f, 0.f);
        if constexpr (DOUT % 2 == 0) {
            if (col < DOUT) v = *(const float2*)(W + (size_t)(k0 + kk) * DOUT + col);
        } else {
            if (col < DOUT)     v.x = W[(size_t)(k0 + kk) * DOUT + col];
            if (col + 1 < DOUT) v.y = W[(size_t)(k0 + kk) * DOUT + col + 1];
        }
        wr[i] = v;
    }
}
template<int DOUT_PAD>
__device__ __forceinline__ void stsW(float* wt, const float2* wr) {
    constexpr int NW = DOUT_PAD / 32;
    constexpr int HALF = DOUT_PAD / 2;
#pragma unroll
    for (int i = 0; i < NW; i++) {
        int idx = threadIdx.x + i * 256;
        int kk = idx / HALF, oc = idx % HALF;
        *(float2*)(wt + kk * DOUT_PAD + 2 * oc) = wr[i];
    }
}

// ================= fused MLP stage v4 =================
// 256 threads; warp tile = 16 rows x (DOUT_PAD/2) cols.
// lane: cl=tid&3 (4 col-lanes), rl=(tid>>2)&7 (8 row-lanes); warp: rb=(tid>>5)&3, cb=tid>>7.
// 2 rows/thread (r0, r0+8); cols/thread = DOUT_PAD/8 contiguous.
// Weight tile double-buffered (2 x 16 x DOUT_PAD), 1 sync per 16-k chunk.
// in_s/out_s may ALIAS (reads complete before final sync; epilogue writes after).
// OMODE: 0 smem out_s; 1 edge final (er/ea split); 2 node final; 3 head final.
template <int DIN, int DOUT, int DOUT_PAD, int ACT, int OMODE>
__device__ __forceinline__ void mlp4(const float* __restrict__ W,
                                     const float* __restrict__ B,
                                     const float* in_s, float* out_s,
                                     float* wt, int tid,
                                     float* g0 = nullptr, float* g1 = nullptr,
                                     const int* rowmap = nullptr, int base = 0) {
    constexpr int NJQ = DOUT_PAD / 32;
    constexpr int WCOLS = DOUT_PAD / 2;
    constexpr int CPT = DOUT_PAD / 8;
    constexpr int NC = DIN / 16;
    const int cl = tid & 3;
    const int rl = (tid >> 2) & 7;
    const int rb = (tid >> 5) & 3;
    const int cb = tid >> 7;
    const int r0 = rb * 16 + rl;
    const int r1 = r0 + 8;
    const int cbase = cb * WCOLS + cl * CPT;

    unsigned long long acc[2][NJQ][2];
#pragma unroll
    for (int r = 0; r < 2; r++)
#pragma unroll
        for (int j = 0; j < NJQ; j++) { acc[r][j][0] = 0ull; acc[r][j][1] = 0ull; }

    float2 wr[NJQ];
    loadW_regs<DOUT, DOUT_PAD>(W, 0, wr);
    stsW<DOUT_PAD>(wt, wr);
    __syncthreads();
    const unsigned wb0 = (unsigned)__cvta_generic_to_shared(wt) + cbase * 4;

    for (int kc = 0; kc < NC; kc++) {
        if (kc + 1 < NC) loadW_regs<DOUT, DOUT_PAD>(W, (kc + 1) * 16, wr);
        const unsigned wb = wb0 + (unsigned)((kc & 1) * 16 * DOUT_PAD * 4);
        const float* a0p = in_s + (size_t)r0 * DIN + kc * 16;
        const float* a1p = in_s + (size_t)r1 * DIN + kc * 16;
#pragma unroll
        for (int kb = 0; kb < 16; kb += 4) {
            float4 a0 = *(const float4*)(a0p + kb);
            float4 a1 = *(const float4*)(a1p + kb);
#pragma unroll
            for (int kk = 0; kk < 4; kk++) {
                unsigned long long p0 = packdup(((const float*)&a0)[kk]);
                unsigned long long p1 = packdup(((const float*)&a1)[kk]);
#pragma unroll
                for (int j = 0; j < NJQ; j++) {
                    unsigned long long w01, w23;
                    lds_wpair(wb + (unsigned)(((kb + kk) * DOUT_PAD + j * 4) * 4), w01, w23);
                    ffma2(acc[0][j][0], p0, w01); ffma2(acc[0][j][1], p0, w23);
                    ffma2(acc[1][j][0], p1, w01); ffma2(acc[1][j][1], p1, w23);
                }
            }
        }
        if (kc + 1 < NC) stsW<DOUT_PAD>(wt + ((kc + 1) & 1) * 16 * DOUT_PAD, wr);
        __syncthreads();
    }
    // epilogue (after final sync: safe even if out_s aliases in_s)
#pragma unroll
    for (int j = 0; j < NJQ; j++) {
#pragma unroll
        for (int h = 0; h < 2; h++) {
            int o = cbase + j * 4 + h * 2;
            float b0 = (o < DOUT) ? B[o] : 0.f;
            float b1 = (o + 1 < DOUT) ? B[o + 1] : 0.f;
#pragma unroll
            for (int r = 0; r < 2; r++) {
                int row = r ? r1 : r0;
                float v0, v1; unpack2(acc[r][j][h], v0, v1);
                v0 += b0; v1 += b1;
                if (ACT == 1) { v0 = fmaxf(v0, 0.f); v1 = fmaxf(v1, 0.f); }
                if (ACT == 2) {
                    v0 = v0 / (1.f + expf(-v0));
                    v1 = v1 / (1.f + expf(-v1));
                }
                if (OMODE == 0) {
                    if (o < DOUT)     out_s[(size_t)row * DOUT + o] = v0;
                    if (o + 1 < DOUT) out_s[(size_t)row * DOUT + o + 1] = v1;
                } else if (OMODE == 1) {       // edge final: DOUT=128, split er/ea
                    int e = base + row;
                    if (o < 64) *(float2*)(g0 + (size_t)e * 64 + o) = make_float2(v0, v1);
                    else        *(float2*)(g1 + (size_t)e * 64 + (o - 64)) = make_float2(v0, v1);
                } else if (OMODE == 2) {       // node final: DOUT=128
                    int node = base + row;
                    if (node < N_NODES)
                        *(float2*)(g0 + (size_t)node * 128 + o) = make_float2(v0, v1);
                } else {                        // head final: DOUT=169
                    int nid = rowmap[row];
                    if (nid >= 0) {
                        if (o < DOUT)     g0[(size_t)nid * 169 + o] = v0;
                        if (o + 1 < DOUT) g0[(size_t)nid * 169 + o + 1] = v1;
                    }
                }
            }
        }
    }
}

// ---------------- degree ----------------
__global__ void zero_deg_kernel() {
    int i = blockIdx.x * blockDim.x + threadIdx.x;
    if (i < N_NODES) g_deg[i] = 0.f;
}
__global__ void deg_kernel(const int* __restrict__ dst) {
    int e = blockIdx.x * blockDim.x + threadIdx.x;
    if (e < N_EDGES) atomicAdd(&g_deg[dst[e]], 1.0f);
}
__global__ void inv_kernel() {
    int i = blockIdx.x * blockDim.x + threadIdx.x;
    if (i < N_NODES) {
        float d = g_deg[i];
        g_inv[i] = 1.0f / sqrtf(d);
        g_rdeg[i] = 1.0f / d;
    }
}

// ---------------- edge stage 0: gather-streamed 384 -> 192 (relu) ----------------
__device__ __forceinline__ float4 es0_gather(const float* __restrict__ nodes,
                                             const float* __restrict__ er,
                                             const float* __restrict__ ea,
                                             const int* sidx, const int* didx,
                                             int e0, int grow, int cb) {
    if (cb < 128)      return *(const float4*)(nodes + (size_t)sidx[grow] * 128 + cb);
    else if (cb < 256) return *(const float4*)(nodes + (size_t)didx[grow] * 128 + (cb - 128));
    else if (cb < 320) return *(const float4*)(er + (size_t)(e0 + grow) * 64 + (cb - 256));
    else               return *(const float4*)(ea + (size_t)(e0 + grow) * 64 + (cb - 320));
}

__device__ __forceinline__ void edge_stage0(const float* __restrict__ nodes,
                                            const float* __restrict__ er,
                                            const float* __restrict__ ea,
                                            const int* sidx, const int* didx, int e0,
                                            const float* __restrict__ W,
                                            const float* __restrict__ B,
                                            float* ibuf,  // 2 * 64 * 16
                                            float* wt,    // 2 * 16 * 192
                                            float* out_s, int tid) {
    constexpr int NJQ = 6, NC = 24;
    const int cl = tid & 3;
    const int rl = (tid >> 2) & 7;
    const int rb = (tid >> 5) & 3;
    const int cb = tid >> 7;
    const int r0 = rb * 16 + rl;
    const int r1 = r0 + 8;
    const int cbase = cb * 96 + cl * 24;
    const int grow = tid >> 2;          // 0..63
    const int gq = (tid & 3) * 4;       // 0,4,8,12

    unsigned long long acc[2][NJQ][2];
#pragma unroll
    for (int r = 0; r < 2; r++)
#pragma unroll
        for (int j = 0; j < NJQ; j++) { acc[r][j][0] = 0ull; acc[r][j][1] = 0ull; }

    float2 wr[6];
    float4 pre = es0_gather(nodes, er, ea, sidx, didx, e0, grow, gq);
    loadW_regs<192, 192>(W, 0, wr);
    *(float4*)(ibuf + grow * 16 + gq) = pre;
    stsW<192>(wt, wr);
    __syncthreads();
    const unsigned wb0 = (unsigned)__cvta_generic_to_shared(wt) + cbase * 4;

    for (int kc = 0; kc < NC; kc++) {
        if (kc + 1 < NC) {
            pre = es0_gather(nodes, er, ea, sidx, didx, e0, grow, (kc + 1) * 16 + gq);
            loadW_regs<192, 192>(W, (kc + 1) * 16, wr);
        }
        const unsigned wb = wb0 + (unsigned)((kc & 1) * 16 * 192 * 4);
        const float* ib = ibuf + (kc & 1) * 1024;
#pragma unroll
        for (int kb = 0; kb < 16; kb += 4) {
            float4 a0 = *(const float4*)(ib + r0 * 16 + kb);
            float4 a1 = *(const float4*)(ib + r1 * 16 + kb);
#pragma unroll
            for (int kk = 0; kk < 4; kk++) {
                unsigned long long p0 = packdup(((const float*)&a0)[kk]);
                unsigned long long p1 = packdup(((const float*)&a1)[kk]);
#pragma unroll
                for (int j = 0; j < NJQ; j++) {
                    unsigned long long w01, w23;
                    lds_wpair(wb + (unsigned)(((kb + kk) * 192 + j * 4) * 4), w01, w23);
                    ffma2(acc[0][j][0], p0, w01); ffma2(acc[0][j][1], p0, w23);
                    ffma2(acc[1][j][0], p1, w01); ffma2(acc[1][j][1], p1, w23);
                }
            }
        }
        if (kc + 1 < NC) {
            *(float4*)(ibuf + ((kc + 1) & 1) * 1024 + grow * 16 + gq) = pre;
            stsW<192>(wt + ((kc + 1) & 1) * 16 * 192, wr);
        }
        __syncthreads();
    }
#pragma unroll
    for (int j = 0; j < NJQ; j++) {
#pragma unroll
        for (int h = 0; h < 2; h++) {
            int o = cbase + j * 4 + h * 2;
            float b0 = B[o], b1 = B[o + 1];
#pragma unroll
            for (int r = 0; r < 2; r++) {
                int row = r ? r1 : r0;
                float v0, v1; unpack2(acc[r][j][h], v0, v1);
                v0 = fmaxf(v0 + b0, 0.f); v1 = fmaxf(v1 + b1, 0.f);
                out_s[(size_t)row * 192 + o] = v0;
                out_s[(size_t)row * 192 + o + 1] = v1;
            }
        }
    }
}

// ---------------- fused edge MLP (layer 0 only; layer-1 output is dead) ----------------
extern "C" __global__ void __launch_bounds__(256, 2)
edge_mlp_kernel(const float* __restrict__ nodes, const float* __restrict__ er,
                const float* __restrict__ ea, const int* __restrict__ src,
                const int* __restrict__ dst,
                const float* W0, const float* B0, const float* W1, const float* B1,
                const float* W2, const float* B2, const float* W3, const float* B3,
                const float* W4, const float* B4, const float* W5, const float* B5,
                float* __restrict__ er_out, float* __restrict__ ea_out) {
    extern __shared__ float smem[];
    float* ibuf = smem;                  // 2*64*16 = 2048 f
    float* wt   = ibuf + 2048;           // 2*16*192 = 6144 f
    float* buf  = wt + 6144;             // 64*192 = 12288 f (aliased across stages)
    __shared__ int sidx[64], didx[64];

    int tid = threadIdx.x;
    int e0 = blockIdx.x * 64;
    if (tid < 64) {
        sidx[tid] = src[e0 + tid];
        didx[tid] = dst[e0 + tid];
    }
    __syncthreads();

    edge_stage0(nodes, er, ea, sidx, didx, e0, W0, B0, ibuf, wt, buf, tid);
    mlp4<192,  96,  96, 1, 0>(W1, B1, buf, buf, wt, tid);
    mlp4< 96,  48,  64, 1, 0>(W2, B2, buf, buf, wt, tid);
    mlp4< 48,  32,  32, 1, 0>(W3, B3, buf, buf, wt, tid);
    mlp4< 32,  64,  64, 1, 0>(W4, B4, buf, buf, wt, tid);
    mlp4< 64, 128, 128, 0, 1>(W5, B5, buf, nullptr, wt, tid, er_out, ea_out, nullptr, e0);
}

// ---------------- message accumulation ----------------
extern "C" __global__ void __launch_bounds__(256)
msg_kernel(const float* __restrict__ nodes, const float* __restrict__ er,
           const float* __restrict__ ea, const int* __restrict__ src,
           const int* __restrict__ dst) {
    int t = threadIdx.x;
    int e = blockIdx.x * 4 + (t >> 6);
    int c4 = (t & 63) * 4;
    int s = src[e];
    int d = dst[e];
    float4 v;
    if (c4 < 128) {
        int j = src[s];            // double gather, matching reference
        v = *(const float4*)(nodes + (size_t)j * 128 + c4);
    } else if (c4 < 192) {
        v = *(const float4*)(er + (size_t)e * 64 + (c4 - 128));
    } else {
        v = *(const float4*)(ea + (size_t)e * 64 + (c4 - 192));
    }
    float r = g_rdeg[s];
    v.x *= r; v.y *= r; v.z *= r; v.w *= r;
    float* p = &g_msg[(size_t)d * 256 + c4];
    asm volatile("red.global.add.v4.f32 [%0], {%1,%2,%3,%4};"
                 :: "l"(p), "f"(v.x), "f"(v.y), "f"(v.z), "f"(v.w) : "memory");
}

// ---------------- node update: silu((msg(+self))*inv @ Wn + bn) ----------------
extern "C" __global__ void __launch_bounds__(256, 2)
node_kernel(const float* __restrict__ nodes_in, const float* __restrict__ Wn,
            const float* __restrict__ bn, float* __restrict__ nodes_out) {
    extern __shared__ float smem[];
    float* buf = smem;               // 64*256 = 16384 f
    float* wt  = buf + 64 * 256;     // 2*16*128 = 4096 f
    int tid = threadIdx.x;
    int n0 = blockIdx.x * 64;

    for (int q = tid; q < 64 * 64; q += 256) {
        int n = q / 64, kq = q % 64;
        int node = n0 + n;
        float4 v = make_float4(0.f, 0.f, 0.f, 0.f);
        if (node < N_NODES) {
            float inv = g_inv[node];
            float4 m = *(const float4*)(g_msg + (size_t)node * 256 + kq * 4);
            if (kq < 32) {
                float4 x = *(const float4*)(nodes_in + (size_t)node * 128 + kq * 4);
                m.x += x.x * inv; m.y += x.y * inv; m.z += x.z * inv; m.w += x.w * inv;
            }
            v = make_float4(m.x * inv, m.y * inv, m.z * inv, m.w * inv);
        }
        *(float4*)(buf + (size_t)q * 4) = v;
    }

    mlp4<256, 128, 128, 2, 2>(Wn, bn, buf, nullptr, wt, tid, nodes_out, nullptr, nullptr, n0);
}

// ---------------- type compaction + heads ----------------
__global__ void zero_cnt_kernel() {
    if (threadIdx.x < 2 && blockIdx.x == 0) g_cnt[threadIdx.x] = 0;
}
__global__ void compact_kernel(const int* __restrict__ atom_type) {
    int i = blockIdx.x * blockDim.x + threadIdx.x;
    if (i < N_NODES) {
        int t = atom_type[i];
        int p = atomicAdd(&g_cnt[t], 1);
        g_perm[t * N_NODES + p] = i;
    }
}

extern "C" __global__ void __launch_bounds__(256, 2)
head_kernel(int t, const float* __restrict__ nodes,
            const float* W0, const float* B0, const float* W1, const float* B1,
            const float* W2, const float* B2, const float* W3, const float* B3,
            const float* W4, const float* B4, float* __restrict__ out) {
    extern __shared__ float smem[];
    float* buf = smem;               // 64*128 = 8192 f
    float* wt  = buf + 64 * 128;     // 2*16*192 = 6144 f
    __shared__ int nid[64];

    int tid = threadIdx.x;
    int cnt = g_cnt[t];
    int i0 = blockIdx.x * 64;
    if (i0 >= cnt) return;
    if (tid < 64) nid[tid] = (i0 + tid < cnt) ? g_perm[t * N_NODES + i0 + tid] : -1;
    __syncthreads();

    for (int q = tid; q < 64 * 32; q += 256) {
        int n = q / 32, cq = q % 32;
        float4 v = make_float4(0.f, 0.f, 0.f, 0.f);
        if (nid[n] >= 0)
            v = *(const float4*)(nodes + (size_t)nid[n] * 128 + cq * 4);
        *(float4*)(buf + (size_t)q * 4) = v;
    }

    mlp4<128, 128, 128, 1, 0>(W0, B0, buf, buf, wt, tid);
    mlp4<128, 128, 128, 1, 0>(W1, B1, buf, buf, wt, tid);
    mlp4<128, 128, 128, 1, 0>(W2, B2, buf, buf, wt, tid);
    mlp4<128, 128, 128, 1, 0>(W3, B3, buf, buf, wt, tid);
    mlp4<128, 169, 192, 0, 3>(W4, B4, buf, nullptr, wt, tid, out, nullptr, nid, 0);
}

// ---------------- launch ----------------
extern "C" void kernel_launch(void* const* d_in, const int* in_sizes, int n_in,
                              void* d_out, int out_size) {
    const float* node_features = (const float*)d_in[0];
    const float* edge_radial   = (const float*)d_in[1];
    const float* edge_angular  = (const float*)d_in[2];
    const int*   edge_index    = (const int*)d_in[3];
    const int*   atom_type     = (const int*)d_in[4];
    const float* We[6]; const float* be[6];
    for (int i = 0; i < 6; i++) { We[i] = (const float*)d_in[5 + 2 * i]; be[i] = (const float*)d_in[6 + 2 * i]; }
    const float* Wn = (const float*)d_in[17];
    const float* bn = (const float*)d_in[18];
    const float* Wh[5]; const float* bh[5];
    for (int i = 0; i < 5; i++) { Wh[i] = (const float*)d_in[19 + 2 * i]; bh[i] = (const float*)d_in[20 + 2 * i]; }
    const int* src = edge_index;
    const int* dst = edge_index + N_EDGES;
    float* out = (float*)d_out;

    const int SM_EDGE = (2048 + 6144 + 12288) * 4;           // 81920 B
    const int SM_NODE = (64 * 256 + 2 * 16 * 128) * 4;       // 81920 B
    const int SM_HEAD = (64 * 128 + 2 * 16 * 192) * 4;       // 57344 B
    cudaFuncSetAttribute(edge_mlp_kernel, cudaFuncAttributeMaxDynamicSharedMemorySize, SM_EDGE);
    cudaFuncSetAttribute(node_kernel,     cudaFuncAttributeMaxDynamicSharedMemorySize, SM_NODE);
    cudaFuncSetAttribute(head_kernel,     cudaFuncAttributeMaxDynamicSharedMemorySize, SM_HEAD);

    // degree (static over layers)
    zero_deg_kernel<<<(N_NODES + 255) / 256, 256>>>();
    deg_kernel<<<(N_EDGES + 255) / 256, 256>>>(dst);
    inv_kernel<<<(N_NODES + 255) / 256, 256>>>();

    float* erA = nullptr; float* eaA = nullptr;
    float* nodesA = nullptr; float* nodesB = nullptr;
    float* msgp = nullptr;
    cudaGetSymbolAddress((void**)&erA, g_erA);
    cudaGetSymbolAddress((void**)&eaA, g_eaA);
    cudaGetSymbolAddress((void**)&nodesA, g_nodesA);
    cudaGetSymbolAddress((void**)&nodesB, g_nodesB);
    cudaGetSymbolAddress((void**)&msgp, g_msg);

    // ---- layer 0 ----
    edge_mlp_kernel<<<N_EDGES / 64, 256, SM_EDGE>>>(
        node_features, edge_radial, edge_angular, src, dst,
        We[0], be[0], We[1], be[1], We[2], be[2],
        We[3], be[3], We[4], be[4], We[5], be[5],
        erA, eaA);
    cudaMemsetAsync(msgp, 0, (size_t)N_NODES * 256 * sizeof(float));
    msg_kernel<<<N_EDGES / 4, 256>>>(node_features, edge_radial, edge_angular, src, dst);
    node_kernel<<<(N_NODES + 63) / 64, 256, SM_NODE>>>(node_features, Wn, bn, nodesA);

    // ---- layer 1 (edge MLP output is unused -> skipped) ----
    cudaMemsetAsync(msgp, 0, (size_t)N_NODES * 256 * sizeof(float));
    msg_kernel<<<N_EDGES / 4, 256>>>(nodesA, erA, eaA, src, dst);
    node_kernel<<<(N_NODES + 63) / 64, 256, SM_NODE>>>(nodesA, Wn + 256 * 128, bn + 128, nodesB);

    // ---- heads (per-type compaction, compute only the selected head) ----
    zero_cnt_kernel<<<1, 32>>>();
    compact_kernel<<<(N_NODES + 255) / 256, 256>>>(atom_type);
    int hblocks = (N_NODES + 63) / 64;
    for (int t = 0; t < 2; t++) {
        head_kernel<<<hblocks, 256, SM_HEAD>>>(
            t, nodesB,
            Wh[0] + (size_t)t * 128 * 128, bh[0] + (size_t)t * 128,
            Wh[1] + (size_t)t * 128 * 128, bh[1] + (size_t)t * 128,
            Wh[2] + (size_t)t * 128 * 128, bh[2] + (size_t)t * 128,
            Wh[3] + (size_t)t * 128 * 128, bh[3] + (size_t)t * 128,
            Wh[4] + (size_t)t * 128 * 169, bh[4] + (size_t)t * 169,
            out);
    }
}

// round 16
// speedup vs baseline: 1.0008x; 1.0008x over previous
#include <cuda_runtime.h>
#include <math.h>

#define N_NODES 50000
#define N_EDGES 400000

// ---------------- scratch (static device globals; no allocation) ----------------
__device__ float g_erA[(size_t)N_EDGES * 64];
__device__ float g_eaA[(size_t)N_EDGES * 64];
__device__ float g_msg[(size_t)N_NODES * 256];
__device__ float g_nodesA[(size_t)N_NODES * 128];
__device__ float g_nodesB[(size_t)N_NODES * 128];
__device__ float g_deg[N_NODES];
__device__ float g_inv[N_NODES];   // 1/sqrt(deg)
__device__ float g_rdeg[N_NODES];  // 1/deg
__device__ int   g_perm[2 * N_NODES];
__device__ int   g_cnt[2];

// ---------------- f32x2 helpers ----------------
__device__ __forceinline__ unsigned long long packdup(float x) {
    unsigned long long r; unsigned int u = __float_as_uint(x);
    asm("mov.b64 %0, {%1, %1};" : "=l"(r) : "r"(u));
    return r;
}
__device__ __forceinline__ void ffma2(unsigned long long& acc, unsigned long long a, unsigned long long w) {
    asm("fma.rn.f32x2 %0, %1, %2, %0;" : "+l"(acc) : "l"(a), "l"(w));
}
__device__ __forceinline__ void unpack2(unsigned long long v, float& lo, float& hi) {
    unsigned int a, b;
    asm("mov.b64 {%0, %1}, %2;" : "=r"(a), "=r"(b) : "l"(v));
    lo = __uint_as_float(a); hi = __uint_as_float(b);
}
__device__ __forceinline__ void lds_wpair(unsigned int addr, unsigned long long& w01, unsigned long long& w23) {
    asm volatile("ld.shared.v2.b64 {%0, %1}, [%2];" : "=l"(w01), "=l"(w23) : "r"(addr));
}

// ---------------- weight staging: gmem -> regs -> smem (ping-pong) ----------------
template<int DOUT, int DOUT_PAD>
__device__ __forceinline__ void loadW_regs(const float* __restrict__ W, int k0, float2* wr) {
    constexpr int NW = DOUT_PAD / 32;
    constexpr int HALF = DOUT_PAD / 2;
#pragma unroll
    for (int i = 0; i < NW; i++) {
        int idx = threadIdx.x + i * 256;
        int kk = idx / HALF, oc = idx % HALF;
        int col = 2 * oc;
        float2 v = make_float2(0.f, 0.f);
        if constexpr (DOUT % 2 == 0) {
            if (col < DOUT) v = *(const float2*)(W + (size_t)(k0 + kk) * DOUT + col);
        } else {
            if (col < DOUT)     v.x = W[(size_t)(k0 + kk) * DOUT + col];
            if (col + 1 < DOUT) v.y = W[(size_t)(k0 + kk) * DOUT + col + 1];
        }
        wr[i] = v;
    }
}
template<int DOUT_PAD>
__device__ __forceinline__ void stsW(float* wt, const float2* wr) {
    constexpr int NW = DOUT_PAD / 32;
    constexpr int HALF = DOUT_PAD / 2;
#pragma unroll
    for (int i = 0; i < NW; i++) {
        int idx = threadIdx.x + i * 256;
        int kk = idx / HALF, oc = idx % HALF;
        *(float2*)(wt + kk * DOUT_PAD + 2 * oc) = wr[i];
    }
}

// ================= fused MLP stage v4 =================
// 256 threads; warp tile = 16 rows x (DOUT_PAD/2) cols.
// lane: cl=tid&3 (4 col-lanes), rl=(tid>>2)&7 (8 row-lanes); warp: rb=(tid>>5)&3, cb=tid>>7.
// 2 rows/thread (r0, r0+8); cols/thread = DOUT_PAD/8 contiguous.
// Weight tile double-buffered (2 x 16 x DOUT_PAD), 1 sync per 16-k chunk.
// in_s/out_s may ALIAS (reads complete before final sync; epilogue writes after).
// OMODE: 0 smem out_s; 1 edge final (er/ea split); 2 node final; 3 head final.
template <int DIN, int DOUT, int DOUT_PAD, int ACT, int OMODE>
__device__ __forceinline__ void mlp4(const float* __restrict__ W,
                                     const float* __restrict__ B,
                                     const float* in_s, float* out_s,
                                     float* wt, int tid,
                                     float* g0 = nullptr, float* g1 = nullptr,
                                     const int* rowmap = nullptr, int base = 0) {
    constexpr int NJQ = DOUT_PAD / 32;
    constexpr int WCOLS = DOUT_PAD / 2;
    constexpr int CPT = DOUT_PAD / 8;
    constexpr int NC = DIN / 16;
    const int cl = tid & 3;
    const int rl = (tid >> 2) & 7;
    const int rb = (tid >> 5) & 3;
    const int cb = tid >> 7;
    const int r0 = rb * 16 + rl;
    const int r1 = r0 + 8;
    const int cbase = cb * WCOLS + cl * CPT;

    unsigned long long acc[2][NJQ][2];
#pragma unroll
    for (int r = 0; r < 2; r++)
#pragma unroll
        for (int j = 0; j < NJQ; j++) { acc[r][j][0] = 0ull; acc[r][j][1] = 0ull; }

    float2 wr[NJQ];
    loadW_regs<DOUT, DOUT_PAD>(W, 0, wr);
    stsW<DOUT_PAD>(wt, wr);
    __syncthreads();
    const unsigned wb0 = (unsigned)__cvta_generic_to_shared(wt) + cbase * 4;

    for (int kc = 0; kc < NC; kc++) {
        if (kc + 1 < NC) loadW_regs<DOUT, DOUT_PAD>(W, (kc + 1) * 16, wr);
        const unsigned wb = wb0 + (unsigned)((kc & 1) * 16 * DOUT_PAD * 4);
        const float* a0p = in_s + (size_t)r0 * DIN + kc * 16;
        const float* a1p = in_s + (size_t)r1 * DIN + kc * 16;
#pragma unroll
        for (int kb = 0; kb < 16; kb += 4) {
            float4 a0 = *(const float4*)(a0p + kb);
            float4 a1 = *(const float4*)(a1p + kb);
#pragma unroll
            for (int kk = 0; kk < 4; kk++) {
                unsigned long long p0 = packdup(((const float*)&a0)[kk]);
                unsigned long long p1 = packdup(((const float*)&a1)[kk]);
#pragma unroll
                for (int j = 0; j < NJQ; j++) {
                    unsigned long long w01, w23;
                    lds_wpair(wb + (unsigned)(((kb + kk) * DOUT_PAD + j * 4) * 4), w01, w23);
                    ffma2(acc[0][j][0], p0, w01); ffma2(acc[0][j][1], p0, w23);
                    ffma2(acc[1][j][0], p1, w01); ffma2(acc[1][j][1], p1, w23);
                }
            }
        }
        if (kc + 1 < NC) stsW<DOUT_PAD>(wt + ((kc + 1) & 1) * 16 * DOUT_PAD, wr);
        __syncthreads();
    }
    // epilogue (after final sync: safe even if out_s aliases in_s)
#pragma unroll
    for (int j = 0; j < NJQ; j++) {
#pragma unroll
        for (int h = 0; h < 2; h++) {
            int o = cbase + j * 4 + h * 2;
            float b0 = (o < DOUT) ? B[o] : 0.f;
            float b1 = (o + 1 < DOUT) ? B[o + 1] : 0.f;
#pragma unroll
            for (int r = 0; r < 2; r++) {
                int row = r ? r1 : r0;
                float v0, v1; unpack2(acc[r][j][h], v0, v1);
                v0 += b0; v1 += b1;
                if (ACT == 1) { v0 = fmaxf(v0, 0.f); v1 = fmaxf(v1, 0.f); }
                if (ACT == 2) {
                    v0 = v0 / (1.f + expf(-v0));
                    v1 = v1 / (1.f + expf(-v1));
                }
                if (OMODE == 0) {
                    if (o < DOUT)     out_s[(size_t)row * DOUT + o] = v0;
                    if (o + 1 < DOUT) out_s[(size_t)row * DOUT + o + 1] = v1;
                } else if (OMODE == 1) {       // edge final: DOUT=128, split er/ea
                    int e = base + row;
                    if (o < 64) *(float2*)(g0 + (size_t)e * 64 + o) = make_float2(v0, v1);
                    else        *(float2*)(g1 + (size_t)e * 64 + (o - 64)) = make_float2(v0, v1);
                } else if (OMODE == 2) {       // node final: DOUT=128
                    int node = base + row;
                    if (node < N_NODES)
                        *(float2*)(g0 + (size_t)node * 128 + o) = make_float2(v0, v1);
                } else {                        // head final: DOUT=169
                    int nid = rowmap[row];
                    if (nid >= 0) {
                        if (o < DOUT)     g0[(size_t)nid * 169 + o] = v0;
                        if (o + 1 < DOUT) g0[(size_t)nid * 169 + o + 1] = v1;
                    }
                }
            }
        }
    }
}

// ---------------- degree ----------------
__global__ void zero_deg_kernel() {
    int i = blockIdx.x * blockDim.x + threadIdx.x;
    if (i < N_NODES) g_deg[i] = 0.f;
}
__global__ void deg_kernel(const int* __restrict__ dst) {
    int e = blockIdx.x * blockDim.x + threadIdx.x;
    if (e < N_EDGES) atomicAdd(&g_deg[dst[e]], 1.0f);
}
__global__ void inv_kernel() {
    int i = blockIdx.x * blockDim.x + threadIdx.x;
    if (i < N_NODES) {
        float d = g_deg[i];
        g_inv[i] = 1.0f / sqrtf(d);
        g_rdeg[i] = 1.0f / d;
    }
}

// ---------------- edge stage 0: gather-streamed 384 -> 192 (relu) ----------------
__device__ __forceinline__ float4 es0_gather(const float* __restrict__ nodes,
                                             const float* __restrict__ er,
                                             const float* __restrict__ ea,
                                             const int* sidx, const int* didx,
                                             int e0, int grow, int cb) {
    if (cb < 128)      return *(const float4*)(nodes + (size_t)sidx[grow] * 128 + cb);
    else if (cb < 256) return *(const float4*)(nodes + (size_t)didx[grow] * 128 + (cb - 128));
    else if (cb < 320) return *(const float4*)(er + (size_t)(e0 + grow) * 64 + (cb - 256));
    else               return *(const float4*)(ea + (size_t)(e0 + grow) * 64 + (cb - 320));
}

__device__ __forceinline__ void edge_stage0(const float* __restrict__ nodes,
                                            const float* __restrict__ er,
                                            const float* __restrict__ ea,
                                            const int* sidx, const int* didx, int e0,
                                            const float* __restrict__ W,
                                            const float* __restrict__ B,
                                            float* ibuf,  // 2 * 64 * 16
                                            float* wt,    // 2 * 16 * 192
                                            float* out_s, int tid) {
    constexpr int NJQ = 6, NC = 24;
    const int cl = tid & 3;
    const int rl = (tid >> 2) & 7;
    const int rb = (tid >> 5) & 3;
    const int cb = tid >> 7;
    const int r0 = rb * 16 + rl;
    const int r1 = r0 + 8;
    const int cbase = cb * 96 + cl * 24;
    const int grow = tid >> 2;          // 0..63
    const int gq = (tid & 3) * 4;       // 0,4,8,12

    unsigned long long acc[2][NJQ][2];
#pragma unroll
    for (int r = 0; r < 2; r++)
#pragma unroll
        for (int j = 0; j < NJQ; j++) { acc[r][j][0] = 0ull; acc[r][j][1] = 0ull; }

    float2 wr[6];
    float4 pre = es0_gather(nodes, er, ea, sidx, didx, e0, grow, gq);
    loadW_regs<192, 192>(W, 0, wr);
    *(float4*)(ibuf + grow * 16 + gq) = pre;
    stsW<192>(wt, wr);
    __syncthreads();
    const unsigned wb0 = (unsigned)__cvta_generic_to_shared(wt) + cbase * 4;

    for (int kc = 0; kc < NC; kc++) {
        if (kc + 1 < NC) {
            pre = es0_gather(nodes, er, ea, sidx, didx, e0, grow, (kc + 1) * 16 + gq);
            loadW_regs<192, 192>(W, (kc + 1) * 16, wr);
        }
        const unsigned wb = wb0 + (unsigned)((kc & 1) * 16 * 192 * 4);
        const float* ib = ibuf + (kc & 1) * 1024;
#pragma unroll
        for (int kb = 0; kb < 16; kb += 4) {
            float4 a0 = *(const float4*)(ib + r0 * 16 + kb);
            float4 a1 = *(const float4*)(ib + r1 * 16 + kb);
#pragma unroll
            for (int kk = 0; kk < 4; kk++) {
                unsigned long long p0 = packdup(((const float*)&a0)[kk]);
                unsigned long long p1 = packdup(((const float*)&a1)[kk]);
#pragma unroll
                for (int j = 0; j < NJQ; j++) {
                    unsigned long long w01, w23;
                    lds_wpair(wb + (unsigned)(((kb + kk) * 192 + j * 4) * 4), w01, w23);
                    ffma2(acc[0][j][0], p0, w01); ffma2(acc[0][j][1], p0, w23);
                    ffma2(acc[1][j][0], p1, w01); ffma2(acc[1][j][1], p1, w23);
                }
            }
        }
        if (kc + 1 < NC) {
            *(float4*)(ibuf + ((kc + 1) & 1) * 1024 + grow * 16 + gq) = pre;
            stsW<192>(wt + ((kc + 1) & 1) * 16 * 192, wr);
        }
        __syncthreads();
    }
#pragma unroll
    for (int j = 0; j < NJQ; j++) {
#pragma unroll
        for (int h = 0; h < 2; h++) {
            int o = cbase + j * 4 + h * 2;
            float b0 = B[o], b1 = B[o + 1];
#pragma unroll
            for (int r = 0; r < 2; r++) {
                int row = r ? r1 : r0;
                float v0, v1; unpack2(acc[r][j][h], v0, v1);
                v0 = fmaxf(v0 + b0, 0.f); v1 = fmaxf(v1 + b1, 0.f);
                out_s[(size_t)row * 192 + o] = v0;
                out_s[(size_t)row * 192 + o + 1] = v1;
            }
        }
    }
}

// ---------------- fused edge MLP (layer 0 only; layer-1 output is dead) ----------------
extern "C" __global__ void __launch_bounds__(256, 2)
edge_mlp_kernel(const float* __restrict__ nodes, const float* __restrict__ er,
                const float* __restrict__ ea, const int* __restrict__ src,
                const int* __restrict__ dst,
                const float* W0, const float* B0, const float* W1, const float* B1,
                const float* W2, const float* B2, const float* W3, const float* B3,
                const float* W4, const float* B4, const float* W5, const float* B5,
                float* __restrict__ er_out, float* __restrict__ ea_out) {
    extern __shared__ float smem[];
    float* ibuf = smem;                  // 2*64*16 = 2048 f
    float* wt   = ibuf + 2048;           // 2*16*192 = 6144 f
    float* buf  = wt + 6144;             // 64*192 = 12288 f (aliased across stages)
    __shared__ int sidx[64], didx[64];

    int tid = threadIdx.x;
    int e0 = blockIdx.x * 64;
    if (tid < 64) {
        sidx[tid] = src[e0 + tid];
        didx[tid] = dst[e0 + tid];
    }
    __syncthreads();

    edge_stage0(nodes, er, ea, sidx, didx, e0, W0, B0, ibuf, wt, buf, tid);
    mlp4<192,  96,  96, 1, 0>(W1, B1, buf, buf, wt, tid);
    mlp4< 96,  48,  64, 1, 0>(W2, B2, buf, buf, wt, tid);
    mlp4< 48,  32,  32, 1, 0>(W3, B3, buf, buf, wt, tid);
    mlp4< 32,  64,  64, 1, 0>(W4, B4, buf, buf, wt, tid);
    mlp4< 64, 128, 128, 0, 1>(W5, B5, buf, nullptr, wt, tid, er_out, ea_out, nullptr, e0);
}

// ---------------- message accumulation ----------------
extern "C" __global__ void __launch_bounds__(256)
msg_kernel(const float* __restrict__ nodes, const float* __restrict__ er,
           const float* __restrict__ ea, const int* __restrict__ src,
           const int* __restrict__ dst) {
    int t = threadIdx.x;
    int e = blockIdx.x * 4 + (t >> 6);
    int c4 = (t & 63) * 4;
    int s = src[e];
    int d = dst[e];
    float4 v;
    if (c4 < 128) {
        int j = src[s];            // double gather, matching reference
        v = *(const float4*)(nodes + (size_t)j * 128 + c4);
    } else if (c4 < 192) {
        v = *(const float4*)(er + (size_t)e * 64 + (c4 - 128));
    } else {
        v = *(const float4*)(ea + (size_t)e * 64 + (c4 - 192));
    }
    float r = g_rdeg[s];
    v.x *= r; v.y *= r; v.z *= r; v.w *= r;
    float* p = &g_msg[(size_t)d * 256 + c4];
    asm volatile("red.global.add.v4.f32 [%0], {%1,%2,%3,%4};"
                 :: "l"(p), "f"(v.x), "f"(v.y), "f"(v.z), "f"(v.w) : "memory");
}

// ---------------- node update: silu((msg(+self))*inv @ Wn + bn) ----------------
extern "C" __global__ void __launch_bounds__(256, 2)
node_kernel(const float* __restrict__ nodes_in, const float* __restrict__ Wn,
            const float* __restrict__ bn, float* __restrict__ nodes_out) {
    extern __shared__ float smem[];
    float* buf = smem;               // 64*256 = 16384 f
    float* wt  = buf + 64 * 256;     // 2*16*128 = 4096 f
    int tid = threadIdx.x;
    int n0 = blockIdx.x * 64;

    for (int q = tid; q < 64 * 64; q += 256) {
        int n = q / 64, kq = q % 64;
        int node = n0 + n;
        float4 v = make_float4(0.f, 0.f, 0.f, 0.f);
        if (node < N_NODES) {
            float inv = g_inv[node];
            float4 m = *(const float4*)(g_msg + (size_t)node * 256 + kq * 4);
            if (kq < 32) {
                float4 x = *(const float4*)(nodes_in + (size_t)node * 128 + kq * 4);
                m.x += x.x * inv; m.y += x.y * inv; m.z += x.z * inv; m.w += x.w * inv;
            }
            v = make_float4(m.x * inv, m.y * inv, m.z * inv, m.w * inv);
        }
        *(float4*)(buf + (size_t)q * 4) = v;
    }

    mlp4<256, 128, 128, 2, 2>(Wn, bn, buf, nullptr, wt, tid, nodes_out, nullptr, nullptr, n0);
}

// ---------------- type compaction + heads ----------------
__global__ void zero_cnt_kernel() {
    if (threadIdx.x < 2 && blockIdx.x == 0) g_cnt[threadIdx.x] = 0;
}
__global__ void compact_kernel(const int* __restrict__ atom_type) {
    int i = blockIdx.x * blockDim.x + threadIdx.x;
    if (i < N_NODES) {
        int t = atom_type[i];
        int p = atomicAdd(&g_cnt[t], 1);
        g_perm[t * N_NODES + p] = i;
    }
}

extern "C" __global__ void __launch_bounds__(256, 2)
head_kernel(int t, const float* __restrict__ nodes,
            const float* W0, const float* B0, const float* W1, const float* B1,
            const float* W2, const float* B2, const float* W3, const float* B3,
            const float* W4, const float* B4, float* __restrict__ out) {
    extern __shared__ float smem[];
    float* buf = smem;               // 64*128 = 8192 f
    float* wt  = buf + 64 * 128;     // 2*16*192 = 6144 f
    __shared__ int nid[64];

    int tid = threadIdx.x;
    int cnt = g_cnt[t];
    int i0 = blockIdx.x * 64;
    if (i0 >= cnt) return;
    if (tid < 64) nid[tid] = (i0 + tid < cnt) ? g_perm[t * N_NODES + i0 + tid] : -1;
    __syncthreads();

    for (int q = tid; q < 64 * 32; q += 256) {
        int n = q / 32, cq = q % 32;
        float4 v = make_float4(0.f, 0.f, 0.f, 0.f);
        if (nid[n] >= 0)
            v = *(const float4*)(nodes + (size_t)nid[n] * 128 + cq * 4);
        *(float4*)(buf + (size_t)q * 4) = v;
    }

    mlp4<128, 128, 128, 1, 0>(W0, B0, buf, buf, wt, tid);
    mlp4<128, 128, 128, 1, 0>(W1, B1, buf, buf, wt, tid);
    mlp4<128, 128, 128, 1, 0>(W2, B2, buf, buf, wt, tid);
    mlp4<128, 128, 128, 1, 0>(W3, B3, buf, buf, wt, tid);
    mlp4<128, 169, 192, 0, 3>(W4, B4, buf, nullptr, wt, tid, out, nullptr, nid, 0);
}

// ---------------- launch ----------------
extern "C" void kernel_launch(void* const* d_in, const int* in_sizes, int n_in,
                              void* d_out, int out_size) {
    const float* node_features = (const float*)d_in[0];
    const float* edge_radial   = (const float*)d_in[1];
    const float* edge_angular  = (const float*)d_in[2];
    const int*   edge_index    = (const int*)d_in[3];
    const int*   atom_type     = (const int*)d_in[4];
    const float* We[6]; const float* be[6];
    for (int i = 0; i < 6; i++) { We[i] = (const float*)d_in[5 + 2 * i]; be[i] = (const float*)d_in[6 + 2 * i]; }
    const float* Wn = (const float*)d_in[17];
    const float* bn = (const float*)d_in[18];
    const float* Wh[5]; const float* bh[5];
    for (int i = 0; i < 5; i++) { Wh[i] = (const float*)d_in[19 + 2 * i]; bh[i] = (const float*)d_in[20 + 2 * i]; }
    const int* src = edge_index;
    const int* dst = edge_index + N_EDGES;
    float* out = (float*)d_out;

    const int SM_EDGE = (2048 + 6144 + 12288) * 4;           // 81920 B
    const int SM_NODE = (64 * 256 + 2 * 16 * 128) * 4;       // 81920 B
    const int SM_HEAD = (64 * 128 + 2 * 16 * 192) * 4;       // 57344 B
    cudaFuncSetAttribute(edge_mlp_kernel, cudaFuncAttributeMaxDynamicSharedMemorySize, SM_EDGE);
    cudaFuncSetAttribute(node_kernel,     cudaFuncAttributeMaxDynamicSharedMemorySize, SM_NODE);
    cudaFuncSetAttribute(head_kernel,     cudaFuncAttributeMaxDynamicSharedMemorySize, SM_HEAD);

    // degree (static over layers)
    zero_deg_kernel<<<(N_NODES + 255) / 256, 256>>>();
    deg_kernel<<<(N_EDGES + 255) / 256, 256>>>(dst);
    inv_kernel<<<(N_NODES + 255) / 256, 256>>>();

    float* erA = nullptr; float* eaA = nullptr;
    float* nodesA = nullptr; float* nodesB = nullptr;
    float* msgp = nullptr;
    cudaGetSymbolAddress((void**)&erA, g_erA);
    cudaGetSymbolAddress((void**)&eaA, g_eaA);
    cudaGetSymbolAddress((void**)&nodesA, g_nodesA);
    cudaGetSymbolAddress((void**)&nodesB, g_nodesB);
    cudaGetSymbolAddress((void**)&msgp, g_msg);

    // ---- layer 0 ----
    edge_mlp_kernel<<<N_EDGES / 64, 256, SM_EDGE>>>(
        node_features, edge_radial, edge_angular, src, dst,
        We[0], be[0], We[1], be[1], We[2], be[2],
        We[3], be[3], We[4], be[4], We[5], be[5],
        erA, eaA);
    cudaMemsetAsync(msgp, 0, (size_t)N_NODES * 256 * sizeof(float));
    msg_kernel<<<N_EDGES / 4, 256>>>(node_features, edge_radial, edge_angular, src, dst);
    node_kernel<<<(N_NODES + 63) / 64, 256, SM_NODE>>>(node_features, Wn, bn, nodesA);

    // ---- layer 1 (edge MLP output is unused -> skipped) ----
    cudaMemsetAsync(msgp, 0, (size_t)N_NODES * 256 * sizeof(float));
    msg_kernel<<<N_EDGES / 4, 256>>>(nodesA, erA, eaA, src, dst);
    node_kernel<<<(N_NODES + 63) / 64, 256, SM_NODE>>>(nodesA, Wn + 256 * 128, bn + 128, nodesB);

    // ---- heads (per-type compaction, compute only the selected head) ----
    zero_cnt_kernel<<<1, 32>>>();
    compact_kernel<<<(N_NODES + 255) / 256, 256>>>(atom_type);
    int hblocks = (N_NODES + 63) / 64;
    for (int t = 0; t < 2; t++) {
        head_kernel<<<hblocks, 256, SM_HEAD>>>(
            t, nodesB,
            Wh[0] + (size_t)t * 128 * 128, bh[0] + (size_t)t * 128,
            Wh[1] + (size_t)t * 128 * 128, bh[1] + (size_t)t * 128,
            Wh[2] + (size_t)t * 128 * 128, bh[2] + (size_t)t * 128,
            Wh[3] + (size_t)t * 128 * 128, bh[3] + (size_t)t * 128,
            Wh[4] + (size_t)t * 128 * 169, bh[4] + (size_t)t * 169,
            out);
    }
}

// round 17
// speedup vs baseline: 1.0014x; 1.0007x over previous
#include <cuda_runtime.h>
#include <math.h>

#define N_NODES 50000
#define N_EDGES 400000

// ---------------- scratch (static device globals; no allocation) ----------------
__device__ float g_erA[(size_t)N_EDGES * 64];
__device__ float g_eaA[(size_t)N_EDGES * 64];
__device__ float g_msg[(size_t)N_NODES * 256];
__device__ float g_nodesA[(size_t)N_NODES * 128];
__device__ float g_nodesB[(size_t)N_NODES * 128];
__device__ float g_deg[N_NODES];
__device__ float g_inv[N_NODES];   // 1/sqrt(deg)
__device__ float g_rdeg[N_NODES];  // 1/deg
__device__ int   g_perm[2 * N_NODES];
__device__ int   g_cnt[2];

// ---------------- f32x2 helpers ----------------
__device__ __forceinline__ unsigned long long packdup(float x) {
    unsigned long long r; unsigned int u = __float_as_uint(x);
    asm("mov.b64 %0, {%1, %1};" : "=l"(r) : "r"(u));
    return r;
}
__device__ __forceinline__ void ffma2(unsigned long long& acc, unsigned long long a, unsigned long long w) {
    asm("fma.rn.f32x2 %0, %1, %2, %0;" : "+l"(acc) : "l"(a), "l"(w));
}
__device__ __forceinline__ void unpack2(unsigned long long v, float& lo, float& hi) {
    unsigned int a, b;
    asm("mov.b64 {%0, %1}, %2;" : "=r"(a), "=r"(b) : "l"(v));
    lo = __uint_as_float(a); hi = __uint_as_float(b);
}
__device__ __forceinline__ void lds_wpair(unsigned int addr, unsigned long long& w01, unsigned long long& w23) {
    asm volatile("ld.shared.v2.b64 {%0, %1}, [%2];" : "=l"(w01), "=l"(w23) : "r"(addr));
}

// ---------------- weight staging: gmem -> regs -> smem (ping-pong) ----------------
template<int DOUT, int DOUT_PAD>
__device__ __forceinline__ void loadW_regs(const float* __restrict__ W, int k0, float2* wr) {
    constexpr int NW = DOUT_PAD / 32;
    constexpr int HALF = DOUT_PAD / 2;
#pragma unroll
    for (int i = 0; i < NW; i++) {
        int idx = threadIdx.x + i * 256;
        int kk = idx / HALF, oc = idx % HALF;
        int col = 2 * oc;
        float2 v = make_float2(0.f, 0.f);
        if constexpr (DOUT % 2 == 0) {
            if (col < DOUT) v = *(const float2*)(W + (size_t)(k0 + kk) * DOUT + col);
        } else {
            if (col < DOUT)     v.x = W[(size_t)(k0 + kk) * DOUT + col];
            if (col + 1 < DOUT) v.y = W[(size_t)(k0 + kk) * DOUT + col + 1];
        }
        wr[i] = v;
    }
}
template<int DOUT_PAD>
__device__ __forceinline__ void stsW(float* wt, const float2* wr) {
    constexpr int NW = DOUT_PAD / 32;
    constexpr int HALF = DOUT_PAD / 2;
#pragma unroll
    for (int i = 0; i < NW; i++) {
        int idx = threadIdx.x + i * 256;
        int kk = idx / HALF, oc = idx % HALF;
        *(float2*)(wt + kk * DOUT_PAD + 2 * oc) = wr[i];
    }
}

// ================= fused MLP stage v4 =================
// 256 threads; warp tile = 16 rows x (DOUT_PAD/2) cols.
// lane: cl=tid&3 (4 col-lanes), rl=(tid>>2)&7 (8 row-lanes); warp: rb=(tid>>5)&3, cb=tid>>7.
// 2 rows/thread (r0, r0+8); cols/thread = DOUT_PAD/8 contiguous.
// Weight tile double-buffered (2 x 16 x DOUT_PAD), 1 sync per 16-k chunk.
// in_s/out_s may ALIAS (reads complete before final sync; epilogue writes after).
// OMODE: 0 smem out_s; 1 edge final (er/ea split); 2 node final; 3 head final.
template <int DIN, int DOUT, int DOUT_PAD, int ACT, int OMODE>
__device__ __forceinline__ void mlp4(const float* __restrict__ W,
                                     const float* __restrict__ B,
                                     const float* in_s, float* out_s,
                                     float* wt, int tid,
                                     float* g0 = nullptr, float* g1 = nullptr,
                                     const int* rowmap = nullptr, int base = 0) {
    constexpr int NJQ = DOUT_PAD / 32;
    constexpr int WCOLS = DOUT_PAD / 2;
    constexpr int CPT = DOUT_PAD / 8;
    constexpr int NC = DIN / 16;
    const int cl = tid & 3;
    const int rl = (tid >> 2) & 7;
    const int rb = (tid >> 5) & 3;
    const int cb = tid >> 7;
    const int r0 = rb * 16 + rl;
    const int r1 = r0 + 8;
    const int cbase = cb * WCOLS + cl * CPT;

    unsigned long long acc[2][NJQ][2];
#pragma unroll
    for (int r = 0; r < 2; r++)
#pragma unroll
        for (int j = 0; j < NJQ; j++) { acc[r][j][0] = 0ull; acc[r][j][1] = 0ull; }

    float2 wr[NJQ];
    loadW_regs<DOUT, DOUT_PAD>(W, 0, wr);
    stsW<DOUT_PAD>(wt, wr);
    __syncthreads();
    const unsigned wb0 = (unsigned)__cvta_generic_to_shared(wt) + cbase * 4;

    for (int kc = 0; kc < NC; kc++) {
        if (kc + 1 < NC) loadW_regs<DOUT, DOUT_PAD>(W, (kc + 1) * 16, wr);
        const unsigned wb = wb0 + (unsigned)((kc & 1) * 16 * DOUT_PAD * 4);
        const float* a0p = in_s + (size_t)r0 * DIN + kc * 16;
        const float* a1p = in_s + (size_t)r1 * DIN + kc * 16;
#pragma unroll
        for (int kb = 0; kb < 16; kb += 4) {
            float4 a0 = *(const float4*)(a0p + kb);
            float4 a1 = *(const float4*)(a1p + kb);
#pragma unroll
            for (int kk = 0; kk < 4; kk++) {
                unsigned long long p0 = packdup(((const float*)&a0)[kk]);
                unsigned long long p1 = packdup(((const float*)&a1)[kk]);
#pragma unroll
                for (int j = 0; j < NJQ; j++) {
                    unsigned long long w01, w23;
                    lds_wpair(wb + (unsigned)(((kb + kk) * DOUT_PAD + j * 4) * 4), w01, w23);
                    ffma2(acc[0][j][0], p0, w01); ffma2(acc[0][j][1], p0, w23);
                    ffma2(acc[1][j][0], p1, w01); ffma2(acc[1][j][1], p1, w23);
                }
            }
        }
        if (kc + 1 < NC) stsW<DOUT_PAD>(wt + ((kc + 1) & 1) * 16 * DOUT_PAD, wr);
        __syncthreads();
    }
    // epilogue (after final sync: safe even if out_s aliases in_s)
#pragma unroll
    for (int j = 0; j < NJQ; j++) {
#pragma unroll
        for (int h = 0; h < 2; h++) {
            int o = cbase + j * 4 + h * 2;
            float b0 = (o < DOUT) ? B[o] : 0.f;
            float b1 = (o + 1 < DOUT) ? B[o + 1] : 0.f;
#pragma unroll
            for (int r = 0; r < 2; r++) {
                int row = r ? r1 : r0;
                float v0, v1; unpack2(acc[r][j][h], v0, v1);
                v0 += b0; v1 += b1;
                if (ACT == 1) { v0 = fmaxf(v0, 0.f); v1 = fmaxf(v1, 0.f); }
                if (ACT == 2) {
                    v0 = v0 / (1.f + expf(-v0));
                    v1 = v1 / (1.f + expf(-v1));
                }
                if (OMODE == 0) {
                    if (o < DOUT)     out_s[(size_t)row * DOUT + o] = v0;
                    if (o + 1 < DOUT) out_s[(size_t)row * DOUT + o + 1] = v1;
                } else if (OMODE == 1) {       // edge final: DOUT=128, split er/ea
                    int e = base + row;
                    if (o < 64) *(float2*)(g0 + (size_t)e * 64 + o) = make_float2(v0, v1);
                    else        *(float2*)(g1 + (size_t)e * 64 + (o - 64)) = make_float2(v0, v1);
                } else if (OMODE == 2) {       // node final: DOUT=128
                    int node = base + row;
                    if (node < N_NODES)
                        *(float2*)(g0 + (size_t)node * 128 + o) = make_float2(v0, v1);
                } else {                        // head final: DOUT=169
                    int nid = rowmap[row];
                    if (nid >= 0) {
                        if (o < DOUT)     g0[(size_t)nid * 169 + o] = v0;
                        if (o + 1 < DOUT) g0[(size_t)nid * 169 + o + 1] = v1;
                    }
                }
            }
        }
    }
}

// ---------------- degree ----------------
__global__ void zero_deg_kernel() {
    int i = blockIdx.x * blockDim.x + threadIdx.x;
    if (i < N_NODES) g_deg[i] = 0.f;
}
__global__ void deg_kernel(const int* __restrict__ dst) {
    int e = blockIdx.x * blockDim.x + threadIdx.x;
    if (e < N_EDGES) atomicAdd(&g_deg[dst[e]], 1.0f);
}
__global__ void inv_kernel() {
    int i = blockIdx.x * blockDim.x + threadIdx.x;
    if (i < N_NODES) {
        float d = g_deg[i];
        g_inv[i] = 1.0f / sqrtf(d);
        g_rdeg[i] = 1.0f / d;
    }
}

// ---------------- edge stage 0: gather-streamed 384 -> 192 (relu) ----------------
__device__ __forceinline__ float4 es0_gather(const float* __restrict__ nodes,
                                             const float* __restrict__ er,
                                             const float* __restrict__ ea,
                                             const int* sidx, const int* didx,
                                             int e0, int grow, int cb) {
    if (cb < 128)      return *(const float4*)(nodes + (size_t)sidx[grow] * 128 + cb);
    else if (cb < 256) return *(const float4*)(nodes + (size_t)didx[grow] * 128 + (cb - 128));
    else if (cb < 320) return *(const float4*)(er + (size_t)(e0 + grow) * 64 + (cb - 256));
    else               return *(const float4*)(ea + (size_t)(e0 + grow) * 64 + (cb - 320));
}

__device__ __forceinline__ void edge_stage0(const float* __restrict__ nodes,
                                            const float* __restrict__ er,
                                            const float* __restrict__ ea,
                                            const int* sidx, const int* didx, int e0,
                                            const float* __restrict__ W,
                                            const float* __restrict__ B,
                                            float* ibuf,  // 2 * 64 * 16
                                            float* wt,    // 2 * 16 * 192
                                            float* out_s, int tid) {
    constexpr int NJQ = 6, NC = 24;
    const int cl = tid & 3;
    const int rl = (tid >> 2) & 7;
    const int rb = (tid >> 5) & 3;
    const int cb = tid >> 7;
    const int r0 = rb * 16 + rl;
    const int r1 = r0 + 8;
    const int cbase = cb * 96 + cl * 24;
    const int grow = tid >> 2;          // 0..63
    const int gq = (tid & 3) * 4;       // 0,4,8,12

    unsigned long long acc[2][NJQ][2];
#pragma unroll
    for (int r = 0; r < 2; r++)
#pragma unroll
        for (int j = 0; j < NJQ; j++) { acc[r][j][0] = 0ull; acc[r][j][1] = 0ull; }

    float2 wr[6];
    float4 pre = es0_gather(nodes, er, ea, sidx, didx, e0, grow, gq);
    loadW_regs<192, 192>(W, 0, wr);
    *(float4*)(ibuf + grow * 16 + gq) = pre;
    stsW<192>(wt, wr);
    __syncthreads();
    const unsigned wb0 = (unsigned)__cvta_generic_to_shared(wt) + cbase * 4;

    for (int kc = 0; kc < NC; kc++) {
        if (kc + 1 < NC) {
            pre = es0_gather(nodes, er, ea, sidx, didx, e0, grow, (kc + 1) * 16 + gq);
            loadW_regs<192, 192>(W, (kc + 1) * 16, wr);
        }
        const unsigned wb = wb0 + (unsigned)((kc & 1) * 16 * 192 * 4);
        const float* ib = ibuf + (kc & 1) * 1024;
#pragma unroll
        for (int kb = 0; kb < 16; kb += 4) {
            float4 a0 = *(const float4*)(ib + r0 * 16 + kb);
            float4 a1 = *(const float4*)(ib + r1 * 16 + kb);
#pragma unroll
            for (int kk = 0; kk < 4; kk++) {
                unsigned long long p0 = packdup(((const float*)&a0)[kk]);
                unsigned long long p1 = packdup(((const float*)&a1)[kk]);
#pragma unroll
                for (int j = 0; j < NJQ; j++) {
                    unsigned long long w01, w23;
                    lds_wpair(wb + (unsigned)(((kb + kk) * 192 + j * 4) * 4), w01, w23);
                    ffma2(acc[0][j][0], p0, w01); ffma2(acc[0][j][1], p0, w23);
                    ffma2(acc[1][j][0], p1, w01); ffma2(acc[1][j][1], p1, w23);
                }
            }
        }
        if (kc + 1 < NC) {
            *(float4*)(ibuf + ((kc + 1) & 1) * 1024 + grow * 16 + gq) = pre;
            stsW<192>(wt + ((kc + 1) & 1) * 16 * 192, wr);
        }
        __syncthreads();
    }
#pragma unroll
    for (int j = 0; j < NJQ; j++) {
#pragma unroll
        for (int h = 0; h < 2; h++) {
            int o = cbase + j * 4 + h * 2;
            float b0 = B[o], b1 = B[o + 1];
#pragma unroll
            for (int r = 0; r < 2; r++) {
                int row = r ? r1 : r0;
                float v0, v1; unpack2(acc[r][j][h], v0, v1);
                v0 = fmaxf(v0 + b0, 0.f); v1 = fmaxf(v1 + b1, 0.f);
                out_s[(size_t)row * 192 + o] = v0;
                out_s[(size_t)row * 192 + o + 1] = v1;
            }
        }
    }
}

// ---------------- fused edge MLP (layer 0 only; layer-1 output is dead) ----------------
extern "C" __global__ void __launch_bounds__(256, 2)
edge_mlp_kernel(const float* __restrict__ nodes, const float* __restrict__ er,
                const float* __restrict__ ea, const int* __restrict__ src,
                const int* __restrict__ dst,
                const float* W0, const float* B0, const float* W1, const float* B1,
                const float* W2, const float* B2, const float* W3, const float* B3,
                const float* W4, const float* B4, const float* W5, const float* B5,
                float* __restrict__ er_out, float* __restrict__ ea_out) {
    extern __shared__ float smem[];
    float* ibuf = smem;                  // 2*64*16 = 2048 f
    float* wt   = ibuf + 2048;           // 2*16*192 = 6144 f
    float* buf  = wt + 6144;             // 64*192 = 12288 f (aliased across stages)
    __shared__ int sidx[64], didx[64];

    int tid = threadIdx.x;
    int e0 = blockIdx.x * 64;
    if (tid < 64) {
        sidx[tid] = src[e0 + tid];
        didx[tid] = dst[e0 + tid];
    }
    __syncthreads();

    edge_stage0(nodes, er, ea, sidx, didx, e0, W0, B0, ibuf, wt, buf, tid);
    mlp4<192,  96,  96, 1, 0>(W1, B1, buf, buf, wt, tid);
    mlp4< 96,  48,  64, 1, 0>(W2, B2, buf, buf, wt, tid);
    mlp4< 48,  32,  32, 1, 0>(W3, B3, buf, buf, wt, tid);
    mlp4< 32,  64,  64, 1, 0>(W4, B4, buf, buf, wt, tid);
    mlp4< 64, 128, 128, 0, 1>(W5, B5, buf, nullptr, wt, tid, er_out, ea_out, nullptr, e0);
}

// ---------------- message accumulation ----------------
extern "C" __global__ void __launch_bounds__(256)
msg_kernel(const float* __restrict__ nodes, const float* __restrict__ er,
           const float* __restrict__ ea, const int* __restrict__ src,
           const int* __restrict__ dst) {
    int t = threadIdx.x;
    int e = blockIdx.x * 4 + (t >> 6);
    int c4 = (t & 63) * 4;
    int s = src[e];
    int d = dst[e];
    float4 v;
    if (c4 < 128) {
        int j = src[s];            // double gather, matching reference
        v = *(const float4*)(nodes + (size_t)j * 128 + c4);
    } else if (c4 < 192) {
        v = *(const float4*)(er + (size_t)e * 64 + (c4 - 128));
    } else {
        v = *(const float4*)(ea + (size_t)e * 64 + (c4 - 192));
    }
    float r = g_rdeg[s];
    v.x *= r; v.y *= r; v.z *= r; v.w *= r;
    float* p = &g_msg[(size_t)d * 256 + c4];
    asm volatile("red.global.add.v4.f32 [%0], {%1,%2,%3,%4};"
                 :: "l"(p), "f"(v.x), "f"(v.y), "f"(v.z), "f"(v.w) : "memory");
}

// ---------------- node update: silu((msg(+self))*inv @ Wn + bn) ----------------
extern "C" __global__ void __launch_bounds__(256, 2)
node_kernel(const float* __restrict__ nodes_in, const float* __restrict__ Wn,
            const float* __restrict__ bn, float* __restrict__ nodes_out) {
    extern __shared__ float smem[];
    float* buf = smem;               // 64*256 = 16384 f
    float* wt  = buf + 64 * 256;     // 2*16*128 = 4096 f
    int tid = threadIdx.x;
    int n0 = blockIdx.x * 64;

    for (int q = tid; q < 64 * 64; q += 256) {
        int n = q / 64, kq = q % 64;
        int node = n0 + n;
        float4 v = make_float4(0.f, 0.f, 0.f, 0.f);
        if (node < N_NODES) {
            float inv = g_inv[node];
            float4 m = *(const float4*)(g_msg + (size_t)node * 256 + kq * 4);
            if (kq < 32) {
                float4 x = *(const float4*)(nodes_in + (size_t)node * 128 + kq * 4);
                m.x += x.x * inv; m.y += x.y * inv; m.z += x.z * inv; m.w += x.w * inv;
            }
            v = make_float4(m.x * inv, m.y * inv, m.z * inv, m.w * inv);
        }
        *(float4*)(buf + (size_t)q * 4) = v;
    }

    mlp4<256, 128, 128, 2, 2>(Wn, bn, buf, nullptr, wt, tid, nodes_out, nullptr, nullptr, n0);
}

// ---------------- type compaction + heads ----------------
__global__ void zero_cnt_kernel() {
    if (threadIdx.x < 2 && blockIdx.x == 0) g_cnt[threadIdx.x] = 0;
}
__global__ void compact_kernel(const int* __restrict__ atom_type) {
    int i = blockIdx.x * blockDim.x + threadIdx.x;
    if (i < N_NODES) {
        int t = atom_type[i];
        int p = atomicAdd(&g_cnt[t], 1);
        g_perm[t * N_NODES + p] = i;
    }
}

extern "C" __global__ void __launch_bounds__(256, 2)
head_kernel(int t, const float* __restrict__ nodes,
            const float* W0, const float* B0, const float* W1, const float* B1,
            const float* W2, const float* B2, const float* W3, const float* B3,
            const float* W4, const float* B4, float* __restrict__ out) {
    extern __shared__ float smem[];
    float* buf = smem;               // 64*128 = 8192 f
    float* wt  = buf + 64 * 128;     // 2*16*192 = 6144 f
    __shared__ int nid[64];

    int tid = threadIdx.x;
    int cnt = g_cnt[t];
    int i0 = blockIdx.x * 64;
    if (i0 >= cnt) return;
    if (tid < 64) nid[tid] = (i0 + tid < cnt) ? g_perm[t * N_NODES + i0 + tid] : -1;
    __syncthreads();

    for (int q = tid; q < 64 * 32; q += 256) {
        int n = q / 32, cq = q % 32;
        float4 v = make_float4(0.f, 0.f, 0.f, 0.f);
        if (nid[n] >= 0)
            v = *(const float4*)(nodes + (size_t)nid[n] * 128 + cq * 4);
        *(float4*)(buf + (size_t)q * 4) = v;
    }

    mlp4<128, 128, 128, 1, 0>(W0, B0, buf, buf, wt, tid);
    mlp4<128, 128, 128, 1, 0>(W1, B1, buf, buf, wt, tid);
    mlp4<128, 128, 128, 1, 0>(W2, B2, buf, buf, wt, tid);
    mlp4<128, 128, 128, 1, 0>(W3, B3, buf, buf, wt, tid);
    mlp4<128, 169, 192, 0, 3>(W4, B4, buf, nullptr, wt, tid, out, nullptr, nid, 0);
}

// ---------------- launch ----------------
extern "C" void kernel_launch(void* const* d_in, const int* in_sizes, int n_in,
                              void* d_out, int out_size) {
    const float* node_features = (const float*)d_in[0];
    const float* edge_radial   = (const float*)d_in[1];
    const float* edge_angular  = (const float*)d_in[2];
    const int*   edge_index    = (const int*)d_in[3];
    const int*   atom_type     = (const int*)d_in[4];
    const float* We[6]; const float* be[6];
    for (int i = 0; i < 6; i++) { We[i] = (const float*)d_in[5 + 2 * i]; be[i] = (const float*)d_in[6 + 2 * i]; }
    const float* Wn = (const float*)d_in[17];
    const float* bn = (const float*)d_in[18];
    const float* Wh[5]; const float* bh[5];
    for (int i = 0; i < 5; i++) { Wh[i] = (const float*)d_in[19 + 2 * i]; bh[i] = (const float*)d_in[20 + 2 * i]; }
    const int* src = edge_index;
    const int* dst = edge_index + N_EDGES;
    float* out = (float*)d_out;

    const int SM_EDGE = (2048 + 6144 + 12288) * 4;           // 81920 B
    const int SM_NODE = (64 * 256 + 2 * 16 * 128) * 4;       // 81920 B
    const int SM_HEAD = (64 * 128 + 2 * 16 * 192) * 4;       // 57344 B
    cudaFuncSetAttribute(edge_mlp_kernel, cudaFuncAttributeMaxDynamicSharedMemorySize, SM_EDGE);
    cudaFuncSetAttribute(node_kernel,     cudaFuncAttributeMaxDynamicSharedMemorySize, SM_NODE);
    cudaFuncSetAttribute(head_kernel,     cudaFuncAttributeMaxDynamicSharedMemorySize, SM_HEAD);

    // degree (static over layers)
    zero_deg_kernel<<<(N_NODES + 255) / 256, 256>>>();
    deg_kernel<<<(N_EDGES + 255) / 256, 256>>>(dst);
    inv_kernel<<<(N_NODES + 255) / 256, 256>>>();

    float* erA = nullptr; float* eaA = nullptr;
    float* nodesA = nullptr; float* nodesB = nullptr;
    float* msgp = nullptr;
    cudaGetSymbolAddress((void**)&erA, g_erA);
    cudaGetSymbolAddress((void**)&eaA, g_eaA);
    cudaGetSymbolAddress((void**)&nodesA, g_nodesA);
    cudaGetSymbolAddress((void**)&nodesB, g_nodesB);
    cudaGetSymbolAddress((void**)&msgp, g_msg);

    // ---- layer 0 ----
    edge_mlp_kernel<<<N_EDGES / 64, 256, SM_EDGE>>>(
        node_features, edge_radial, edge_angular, src, dst,
        We[0], be[0], We[1], be[1], We[2], be[2],
        We[3], be[3], We[4], be[4], We[5], be[5],
        erA, eaA);
    cudaMemsetAsync(msgp, 0, (size_t)N_NODES * 256 * sizeof(float));
    msg_kernel<<<N_EDGES / 4, 256>>>(node_features, edge_radial, edge_angular, src, dst);
    node_kernel<<<(N_NODES + 63) / 64, 256, SM_NODE>>>(node_features, Wn, bn, nodesA);

    // ---- layer 1 (edge MLP output is unused -> skipped) ----
    cudaMemsetAsync(msgp, 0, (size_t)N_NODES * 256 * sizeof(float));
    msg_kernel<<<N_EDGES / 4, 256>>>(nodesA, erA, eaA, src, dst);
    node_kernel<<<(N_NODES + 63) / 64, 256, SM_NODE>>>(nodesA, Wn + 256 * 128, bn + 128, nodesB);

    // ---- heads (per-type compaction, compute only the selected head) ----
    zero_cnt_kernel<<<1, 32>>>();
    compact_kernel<<<(N_NODES + 255) / 256, 256>>>(atom_type);
    int hblocks = (N_NODES + 63) / 64;
    for (int t = 0; t < 2; t++) {
        head_kernel<<<hblocks, 256, SM_HEAD>>>(
            t, nodesB,
            Wh[0] + (size_t)t * 128 * 128, bh[0] + (size_t)t * 128,
            Wh[1] + (size_t)t * 128 * 128, bh[1] + (size_t)t * 128,
            Wh[2] + (size_t)t * 128 * 128, bh[2] + (size_t)t * 128,
            Wh[3] + (size_t)t * 128 * 128, bh[3] + (size_t)t * 128,
            Wh[4] + (size_t)t * 128 * 169, bh[4] + (size_t)t * 169,
            out);
    }
}